// round 8
// baseline (speedup 1.0000x reference)
#include <cuda_runtime.h>
#include <cuda_fp16.h>
#include <cstdint>
#include <cstddef>

#define B_SZ 1024
#define NF   800
#define L1D  1024
#define K1   480          // tensor-path K range [0, K1); FFMA path [K1, NF)
#define NT_IT (K1 / 16)   // 30 tensor k-iterations
#define NF_IT ((NF - K1) / 16)  // 20 FFMA k-iterations

// Scratch (no allocation allowed — __device__ globals)
__device__ __half g_a[B_SZ * NF];      // vals fp16 (RN), (B,800) row-major
__device__ float  g_vals[B_SZ * NF];   // vals fp32 exact, (B,800)
__device__ __half g_bh[L1D * K1];      // ft_w^T hi, (n,k) k-contig, k<K1
__device__ __half g_bl[L1D * K1];      // ft_w^T lo
__device__ float  g_pa[B_SZ * L1D];    // partial features (tensor half), raw
__device__ float  g_pb[B_SZ * L1D];    // partial features (FFMA half), raw

// ---------------------------------------------------------------------------
// Kernel 0: transpose ft_w rows k<K1 (-> 1024xK1) and split into fp16 hi/lo.
// ---------------------------------------------------------------------------
__global__ __launch_bounds__(256) void prep_bt_kernel(const float* __restrict__ w) {
    __shared__ float ts[32][33];
    int tx = threadIdx.x & 31, ty = threadIdx.x >> 5;   // 32 x 8
    int kbase = blockIdx.y * 32, nbase = blockIdx.x * 32;
#pragma unroll
    for (int i = 0; i < 4; i++)
        ts[ty + i * 8][tx] = w[(size_t)(kbase + ty + i * 8) * L1D + nbase + tx];
    __syncthreads();
#pragma unroll
    for (int i = 0; i < 4; i++) {
        int n = nbase + ty + i * 8;
        int k = kbase + tx;
        float v = ts[tx][ty + i * 8];
        __half h = __float2half_rn(v);
        g_bh[(size_t)n * K1 + k] = h;
        g_bl[(size_t)n * K1 + k] = __float2half_rn(v - __half2float(h));
    }
}

// ---------------------------------------------------------------------------
// Kernel 1: conv(3x3,s10,p1) + clip + sigmoid gate -> fp16 + fp32 vals.
// ---------------------------------------------------------------------------
__global__ __launch_bounds__(128) void conv_act_kernel(
    const float* __restrict__ images, const float* __restrict__ conv_w) {
    __shared__ float w[216];
    __shared__ float s[30][3][98];
    int t = threadIdx.x;
    int b = blockIdx.x;
    for (int i = t; i < 216; i += 128) w[i] = conv_w[i];
    for (int i = t; i < 3 * 98; i += 128) s[0][i / 98][i % 98] = 0.f;
    for (int i = t; i < 30 * 3; i += 128) s[i / 3][i % 3][0] = 0.f;
    __syncthreads();

    const float* img = images + (size_t)b * 3 * 96 * 96;
    for (int i = t; i < 29 * 3 * 96; i += 128) {
        int rr = i / 288 + 1; int rem = i - (rr - 1) * 288;
        int c = rem / 96;  int x = rem - c * 96;
        int iy = (rr / 3) * 10 - 1 + rr % 3;
        s[rr][c][x + 1] = __ldg(img + c * 9216 + iy * 96 + x);
    }
    __syncthreads();

    if (t < 100) {
        int oy = t / 10, ox = t - oy * 10;
        float acc[8];
#pragma unroll
        for (int c8 = 0; c8 < 8; c8++) acc[c8] = 0.f;
#pragma unroll
        for (int ky = 0; ky < 3; ky++) {
            const float (*srow)[98] = s[3 * oy + ky];
#pragma unroll
            for (int ic = 0; ic < 3; ic++) {
#pragma unroll
                for (int kx = 0; kx < 3; kx++) {
                    float v = srow[ic][10 * ox + kx];
#pragma unroll
                    for (int c8 = 0; c8 < 8; c8++)
                        acc[c8] = fmaf(v, w[c8 * 27 + ic * 9 + ky * 3 + kx], acc[c8]);
                }
            }
        }
#pragma unroll
        for (int c8 = 0; c8 < 8; c8++) {
            float x  = fminf(fmaxf(acc[c8], -1.f), 1.f);
            float sg = 1.f / (1.f + __expf(-10.f * x));
            float vv = (sg > 0.5f) ? sg : 0.f;
            size_t idx = (size_t)b * NF + c8 * 100 + t;
            g_vals[idx] = vv;
            g_a[idx] = __float2half_rn(vv);
        }
    }
}

// ---------------------------------------------------------------------------
// Kernel 2: heterogeneous GEMM, 256 CTAs x 256 thr.
//  CTA < 128 : tensor path, k in [0,K1). BM=64 BN=128, 8 warps (2x4), 32x32
//              warp tiles, D = A*Bh + A*Bl via m16n8k16, raw partial -> g_pa.
//  CTA >= 128: FFMA fp32 path, k in [K1,NF). BM=128 BN=64, 8x4 thread tile,
//              exact fp32, raw partial -> g_pb.
// ---------------------------------------------------------------------------
__device__ __forceinline__ void mma_f16(float* d, const uint32_t* a, const uint32_t* b) {
    asm volatile(
        "mma.sync.aligned.m16n8k16.row.col.f32.f16.f16.f32 "
        "{%0,%1,%2,%3}, {%4,%5,%6,%7}, {%8,%9}, {%0,%1,%2,%3};\n"
        : "+f"(d[0]), "+f"(d[1]), "+f"(d[2]), "+f"(d[3])
        : "r"(a[0]), "r"(a[1]), "r"(a[2]), "r"(a[3]), "r"(b[0]), "r"(b[1]));
}
#define CP16(dst, src) \
    asm volatile("cp.async.ca.shared.global [%0], [%1], 16;\n" :: "r"(dst), "l"(src))

__global__ __launch_bounds__(256) void feat_gemm_kernel(const float* __restrict__ ftw) {
    __shared__ __align__(16) uint32_t sm[7680];   // 30720 B union

    const int t = threadIdx.x, lane = t & 31, wid = t >> 5;
    const int bid = blockIdx.x;

    if (bid < 128) {
        // ================= tensor path =================
        uint32_t* As = sm;            // 2 x 64 x 12
        uint32_t* Bh = sm + 1536;     // 2 x 128 x 12
        uint32_t* Bl = sm + 4608;     // 2 x 128 x 12
        const int wm = wid >> 2, wn = wid & 3;   // 2 x 4 warps
        const int bm = (bid >> 3) * 64, bn = (bid & 7) * 128;

        float acc[2][4][4];
#pragma unroll
        for (int f = 0; f < 2; f++)
#pragma unroll
            for (int j = 0; j < 4; j++)
#pragma unroll
                for (int e = 0; e < 4; e++) acc[f][j][e] = 0.f;

        const int row = t >> 1, seg = t & 1;     // B: 128 rows x 2 segs
        const __half* a_src  = g_a  + (size_t)(bm + row) * NF + seg * 8;  // t<128
        const __half* bh_src = g_bh + (size_t)(bn + row) * K1 + seg * 8;
        const __half* bl_src = g_bl + (size_t)(bn + row) * K1 + seg * 8;
        uint32_t a_dst[2], bh_dst[2], bl_dst[2];
#pragma unroll
        for (int s2 = 0; s2 < 2; s2++) {
            a_dst[s2]  = (uint32_t)__cvta_generic_to_shared(&As[s2 * 768 + row * 12 + seg * 4]);
            bh_dst[s2] = (uint32_t)__cvta_generic_to_shared(&Bh[s2 * 1536 + row * 12 + seg * 4]);
            bl_dst[s2] = (uint32_t)__cvta_generic_to_shared(&Bl[s2 * 1536 + row * 12 + seg * 4]);
        }

#define T_STAGE(s2, k0)                                      \
    do {                                                     \
        if (t < 128) CP16(a_dst[s2], a_src + (k0));          \
        CP16(bh_dst[s2], bh_src + (k0));                     \
        CP16(bl_dst[s2], bl_src + (k0));                     \
        asm volatile("cp.async.commit_group;\n");            \
    } while (0)

        T_STAGE(0, 0);

        const int r0 = wm * 32 + (lane >> 2);
        const int nb = wn * 32 + (lane >> 2);
        const int j0 = lane & 3;

        for (int it = 0; it < NT_IT; it++) {
            int buf = it & 1;
            if (it < NT_IT - 1) {
                T_STAGE(buf ^ 1, (it + 1) * 16);
                asm volatile("cp.async.wait_group 1;\n");
            } else {
                asm volatile("cp.async.wait_group 0;\n");
            }
            __syncthreads();

            uint32_t af[2][4];
            const uint32_t* Ab = As + buf * 768;
#pragma unroll
            for (int f = 0; f < 2; f++) {
                int r = r0 + f * 16;
                af[f][0] = Ab[r * 12 + j0];        af[f][1] = Ab[(r + 8) * 12 + j0];
                af[f][2] = Ab[r * 12 + j0 + 4];    af[f][3] = Ab[(r + 8) * 12 + j0 + 4];
            }
            uint32_t bhf[4][2], blf[4][2];
            const uint32_t* Bhb = Bh + buf * 1536;
            const uint32_t* Blb = Bl + buf * 1536;
#pragma unroll
            for (int j = 0; j < 4; j++) {
                int r = nb + j * 8;
                bhf[j][0] = Bhb[r * 12 + j0]; bhf[j][1] = Bhb[r * 12 + j0 + 4];
                blf[j][0] = Blb[r * 12 + j0]; blf[j][1] = Blb[r * 12 + j0 + 4];
            }
#pragma unroll
            for (int f = 0; f < 2; f++)
#pragma unroll
                for (int j = 0; j < 4; j++) {
                    mma_f16(acc[f][j], af[f], bhf[j]);
                    mma_f16(acc[f][j], af[f], blf[j]);
                }
            __syncthreads();
        }

        int q = lane & 3, g = lane >> 2;
#pragma unroll
        for (int f = 0; f < 2; f++) {
            int row0 = bm + wm * 32 + f * 16 + g;
#pragma unroll
            for (int j = 0; j < 4; j++) {
                int col = bn + wn * 32 + j * 8 + 2 * q;
                float2 o0 = {acc[f][j][0], acc[f][j][1]};
                float2 o1 = {acc[f][j][2], acc[f][j][3]};
                *(float2*)(g_pa + (size_t)row0 * L1D + col) = o0;
                *(float2*)(g_pa + (size_t)(row0 + 8) * L1D + col) = o1;
            }
        }
    } else {
        // ================= FFMA fp32 path =================
        float (*Af)[132] = (float (*)[132])sm;          // 16 x 132
        float (*Bf)[64]  = (float (*)[64])(sm + 2112);  // 16 x 64
        const int fb = bid - 128;
        const int bm = (fb >> 4) * 128, bn = (fb & 15) * 64;
        const int tx = t & 15, ty = t >> 4;

        float acc[8][4];
#pragma unroll
        for (int i = 0; i < 8; i++)
#pragma unroll
            for (int j = 0; j < 4; j++) acc[i][j] = 0.f;

        for (int it = 0; it < NF_IT; it++) {
            const int k0 = K1 + it * 16;
#pragma unroll
            for (int v = 0; v < 2; v++) {
                int lin = t + v * 256;
                int r = lin >> 2;
                int q = (lin & 3) << 2;
                const float4 a4 = *(const float4*)(g_vals + (size_t)(bm + r) * NF + k0 + q);
                Af[q + 0][r] = a4.x; Af[q + 1][r] = a4.y;
                Af[q + 2][r] = a4.z; Af[q + 3][r] = a4.w;
            }
            {
                int r = t >> 4;
                int c = (t & 15) << 2;
                *(float4*)(&Bf[r][c]) = *(const float4*)(ftw + (size_t)(k0 + r) * L1D + bn + c);
            }
            __syncthreads();

#pragma unroll
            for (int kk = 0; kk < 16; kk++) {
                float4 b4 = *(const float4*)(&Bf[kk][tx << 2]);
                float4 a0 = *(const float4*)(&Af[kk][ty << 3]);
                float4 a1 = *(const float4*)(&Af[kk][(ty << 3) + 4]);
                float a[8] = {a0.x, a0.y, a0.z, a0.w, a1.x, a1.y, a1.z, a1.w};
                float bb[4] = {b4.x, b4.y, b4.z, b4.w};
#pragma unroll
                for (int i = 0; i < 8; i++)
#pragma unroll
                    for (int j = 0; j < 4; j++)
                        acc[i][j] = fmaf(a[i], bb[j], acc[i][j]);
            }
            __syncthreads();
        }

#pragma unroll
        for (int i = 0; i < 8; i++) {
            int r = bm + (ty << 3) + i;
            float4 o = {acc[i][0], acc[i][1], acc[i][2], acc[i][3]};
            *(float4*)(g_pb + (size_t)r * L1D + bn + (tx << 2)) = o;
        }
    }
}

// ---------------------------------------------------------------------------
// Kernel 3: tail MLP + fused bias/clip. 8 warps per sample, 1024 CTAs.
// l0[j] = clip(g_pa[j]+g_pb[j]+ft_b[j], 0, 1). Warp q owns e in [4q, 4q+4).
// ---------------------------------------------------------------------------
__global__ __launch_bounds__(256) void tail_kernel(
    const float* __restrict__ ftb,
    const float* __restrict__ w1, const float* __restrict__ b1,
    const float* __restrict__ w2, const float* __restrict__ b2,
    const float* __restrict__ w3, const float* __restrict__ b3,
    float* __restrict__ out) {
    __shared__ float part[8][15];
    __shared__ float h1s[15];

    const int t = threadIdx.x, lane = t & 31, q = t >> 5;
    const int sample = blockIdx.x;
    const float* pa = g_pa + (size_t)sample * L1D;
    const float* pb = g_pb + (size_t)sample * L1D;
    const float KCst = 127.f / 128.f;

#define L0(j) fminf(fmaxf(pa[j] + pb[j] + __ldg(ftb + (j)), 0.f), 1.f)

    float c[4];
    if (q < 4) {
#pragma unroll
        for (int i = 0; i < 4; i++) {
            int e = q * 4 + i;
            c[i] = L0(e * 32 + lane) * L0((e + 16) * 32 + lane) * KCst;
        }
    } else {
#pragma unroll
        for (int i = 0; i < 4; i++) {
            int e = (q - 4) * 4 + i;
            c[i] = L0(e * 32 + lane) * KCst;
        }
    }

    float a[15];
#pragma unroll
    for (int o = 0; o < 15; o++) a[o] = 0.f;
    const int jbase = q * 128 + lane;
#pragma unroll
    for (int i = 0; i < 4; i++) {
#pragma unroll
        for (int o = 0; o < 15; o++)
            a[o] = fmaf(c[i], __ldg(w1 + (size_t)o * L1D + jbase + i * 32), a[o]);
    }
#pragma unroll
    for (int s = 16; s; s >>= 1)
#pragma unroll
        for (int o = 0; o < 15; o++)
            a[o] += __shfl_xor_sync(0xffffffffu, a[o], s);
    if (lane < 15) part[q][lane] = a[lane];
    __syncthreads();

    if (q == 0) {
        if (lane < 15) {
            float h = __ldg(b1 + lane);
#pragma unroll
            for (int p = 0; p < 8; p++) h += part[p][lane];
            h1s[lane] = fmaxf(h, 0.f);
        }
        __syncwarp();
        float h2 = __ldg(b2 + lane);
#pragma unroll
        for (int k = 0; k < 15; k++)
            h2 = fmaf(h1s[k], __ldg(w2 + lane * 15 + k), h2);
        h2 = fmaxf(h2, 0.f);
        float ov = h2 * __ldg(w3 + lane);
#pragma unroll
        for (int s = 16; s; s >>= 1) ov += __shfl_xor_sync(0xffffffffu, ov, s);
        if (lane == 0) out[sample] = ov + __ldg(b3);
    }
}

// ---------------------------------------------------------------------------
extern "C" void kernel_launch(void* const* d_in, const int* in_sizes, int n_in,
                              void* d_out, int out_size) {
    const float *images = 0, *conv_w = 0, *ft_w = 0, *ft_b = 0;
    const float *w1 = 0, *b1 = 0, *w2 = 0, *b2 = 0, *w3 = 0, *b3 = 0;

    for (int i = 0; i < n_in; i++) {
        const float* p = (const float*)d_in[i];
        switch (in_sizes[i]) {
            case 28311552: images = p; break;
            case 216:      conv_w = p; break;
            case 819200:   ft_w   = p; break;
            case 1024:     ft_b   = p; break;
            case 15360:    w1     = p; break;
            case 15:       b1     = p; break;
            case 480:      w2     = p; break;
            case 32:       if (!b2) b2 = p; else w3 = p; break;
            case 1:        b3     = p; break;
            default: break;
        }
    }
    float* out = (float*)d_out;

    dim3 gt(L1D / 32, K1 / 32);      // 32 x 15 (only k < K1 needs hi/lo)
    prep_bt_kernel<<<gt, 256>>>(ft_w);
    conv_act_kernel<<<B_SZ, 128>>>(images, conv_w);

    feat_gemm_kernel<<<256, 256>>>(ft_w);

    tail_kernel<<<B_SZ, 256>>>(ft_b, w1, b1, w2, b2, w3, b3, out);
}

// round 9
// speedup vs baseline: 1.0813x; 1.0813x over previous
#include <cuda_runtime.h>
#include <cuda_fp16.h>
#include <cstdint>
#include <cstddef>

#define B_SZ 1024
#define NF   800
#define L1D  1024
#define K1   448               // tensor-path K in [0,K1); FFMA path [K1,NF)
#define NT_IT (K1 / 16)        // 28
#define NF_IT ((NF - K1) / 16) // 22

// Scratch (no allocation allowed — __device__ globals)
__device__ __half g_a[B_SZ * NF];      // vals fp16 (RN)
__device__ float  g_vals[B_SZ * NF];   // vals fp32 exact
__device__ __half g_bh[L1D * K1];      // ft_w^T hi, (n,k) k-contig, k<K1
__device__ __half g_bl[L1D * K1];      // ft_w^T lo
__device__ float  g_pa[B_SZ * L1D];    // partial features (tensor), raw
__device__ float  g_pb[B_SZ * L1D];    // partial features (FFMA), raw

// ---------------------------------------------------------------------------
// Kernel 0: transpose ft_w rows k<K1 and split into fp16 hi/lo.
// ---------------------------------------------------------------------------
__global__ __launch_bounds__(256) void prep_bt_kernel(const float* __restrict__ w) {
    __shared__ float ts[32][33];
    int tx = threadIdx.x & 31, ty = threadIdx.x >> 5;   // 32 x 8
    int kbase = blockIdx.y * 32, nbase = blockIdx.x * 32;
#pragma unroll
    for (int i = 0; i < 4; i++)
        ts[ty + i * 8][tx] = w[(size_t)(kbase + ty + i * 8) * L1D + nbase + tx];
    __syncthreads();
#pragma unroll
    for (int i = 0; i < 4; i++) {
        int n = nbase + ty + i * 8;
        int k = kbase + tx;
        float v = ts[tx][ty + i * 8];
        __half h = __float2half_rn(v);
        g_bh[(size_t)n * K1 + k] = h;
        g_bl[(size_t)n * K1 + k] = __float2half_rn(v - __half2float(h));
    }
}

// ---------------------------------------------------------------------------
// Kernel 1: conv(3x3,s10,p1) + clip + sigmoid gate -> fp16 + fp32 vals.
// ---------------------------------------------------------------------------
__global__ __launch_bounds__(128) void conv_act_kernel(
    const float* __restrict__ images, const float* __restrict__ conv_w) {
    __shared__ float w[216];
    __shared__ float s[30][3][98];
    int t = threadIdx.x;
    int b = blockIdx.x;
    for (int i = t; i < 216; i += 128) w[i] = conv_w[i];
    for (int i = t; i < 3 * 98; i += 128) s[0][i / 98][i % 98] = 0.f;
    for (int i = t; i < 30 * 3; i += 128) s[i / 3][i % 3][0] = 0.f;
    __syncthreads();

    const float* img = images + (size_t)b * 3 * 96 * 96;
    for (int i = t; i < 29 * 3 * 96; i += 128) {
        int rr = i / 288 + 1; int rem = i - (rr - 1) * 288;
        int c = rem / 96;  int x = rem - c * 96;
        int iy = (rr / 3) * 10 - 1 + rr % 3;
        s[rr][c][x + 1] = __ldg(img + c * 9216 + iy * 96 + x);
    }
    __syncthreads();

    if (t < 100) {
        int oy = t / 10, ox = t - oy * 10;
        float acc[8];
#pragma unroll
        for (int c8 = 0; c8 < 8; c8++) acc[c8] = 0.f;
#pragma unroll
        for (int ky = 0; ky < 3; ky++) {
            const float (*srow)[98] = s[3 * oy + ky];
#pragma unroll
            for (int ic = 0; ic < 3; ic++) {
#pragma unroll
                for (int kx = 0; kx < 3; kx++) {
                    float v = srow[ic][10 * ox + kx];
#pragma unroll
                    for (int c8 = 0; c8 < 8; c8++)
                        acc[c8] = fmaf(v, w[c8 * 27 + ic * 9 + ky * 3 + kx], acc[c8]);
                }
            }
        }
#pragma unroll
        for (int c8 = 0; c8 < 8; c8++) {
            float x  = fminf(fmaxf(acc[c8], -1.f), 1.f);
            float sg = 1.f / (1.f + __expf(-10.f * x));
            float vv = (sg > 0.5f) ? sg : 0.f;
            size_t idx = (size_t)b * NF + c8 * 100 + t;
            g_vals[idx] = vv;
            g_a[idx] = __float2half_rn(vv);
        }
    }
}

// ---------------------------------------------------------------------------
// Kernel 2: fused heterogeneous GEMM. 256 CTAs (16x16 tiles of 64x64), 256 thr.
//  Warps 0-3 (thr 0-127):  tensor path, k in [0,K1).  D = A*Bh + A*Bl
//                          via m16n8k16, warp tile 32x32. -> g_pa (raw)
//  Warps 4-7 (thr 128-255): fp32 FFMA path, k in [K1,NF). exact. -> g_pb (raw)
// Groups sync independently via named barriers 1 and 2.
// ---------------------------------------------------------------------------
__device__ __forceinline__ void mma_f16(float* d, const uint32_t* a, const uint32_t* b) {
    asm volatile(
        "mma.sync.aligned.m16n8k16.row.col.f32.f16.f16.f32 "
        "{%0,%1,%2,%3}, {%4,%5,%6,%7}, {%8,%9}, {%0,%1,%2,%3};\n"
        : "+f"(d[0]), "+f"(d[1]), "+f"(d[2]), "+f"(d[3])
        : "r"(a[0]), "r"(a[1]), "r"(a[2]), "r"(a[3]), "r"(b[0]), "r"(b[1]));
}
#define CP16(dst, src) \
    asm volatile("cp.async.ca.shared.global [%0], [%1], 16;\n" :: "r"(dst), "l"(src))
#define BAR1() asm volatile("bar.sync 1, 128;" ::: "memory")
#define BAR2() asm volatile("bar.sync 2, 128;" ::: "memory")

__global__ __launch_bounds__(256) void feat_gemm_kernel(const float* __restrict__ ftw) {
    __shared__ uint32_t As[2][64][12];
    __shared__ uint32_t Bh[2][64][12];
    __shared__ uint32_t Bl[2][64][12];
    __shared__ float    Af[16][68];
    __shared__ float    Bf[16][64];

    const int t = threadIdx.x, lane = t & 31;
    const int bid = blockIdx.x;
    const int bm = (bid >> 4) * 64, bn = (bid & 15) * 64;

    if (t < 128) {
        // ================= tensor path, k in [0, K1) =================
        const int widt = t >> 5;
        const int wm = widt >> 1, wn = widt & 1;   // 2 x 2 warps, 32x32 tiles

        float acc[2][4][4];
#pragma unroll
        for (int f = 0; f < 2; f++)
#pragma unroll
            for (int j = 0; j < 4; j++)
#pragma unroll
                for (int e = 0; e < 4; e++) acc[f][j][e] = 0.f;

        const int row = t >> 1, seg = t & 1;   // 64 rows x 2 segs per array
        const __half* a_src  = g_a  + (size_t)(bm + row) * NF + seg * 8;
        const __half* bh_src = g_bh + (size_t)(bn + row) * K1 + seg * 8;
        const __half* bl_src = g_bl + (size_t)(bn + row) * K1 + seg * 8;
        uint32_t a_dst[2], bh_dst[2], bl_dst[2];
#pragma unroll
        for (int s2 = 0; s2 < 2; s2++) {
            a_dst[s2]  = (uint32_t)__cvta_generic_to_shared(&As[s2][row][seg * 4]);
            bh_dst[s2] = (uint32_t)__cvta_generic_to_shared(&Bh[s2][row][seg * 4]);
            bl_dst[s2] = (uint32_t)__cvta_generic_to_shared(&Bl[s2][row][seg * 4]);
        }

#define T_STAGE(s2, k0)                                      \
    do {                                                     \
        CP16(a_dst[s2],  a_src  + (k0));                     \
        CP16(bh_dst[s2], bh_src + (k0));                     \
        CP16(bl_dst[s2], bl_src + (k0));                     \
        asm volatile("cp.async.commit_group;\n");            \
    } while (0)

        T_STAGE(0, 0);

        const int r0 = wm * 32 + (lane >> 2);
        const int nb = wn * 32 + (lane >> 2);
        const int j0 = lane & 3;

        for (int it = 0; it < NT_IT; it++) {
            int buf = it & 1;
            if (it < NT_IT - 1) {
                T_STAGE(buf ^ 1, (it + 1) * 16);
                asm volatile("cp.async.wait_group 1;\n");
            } else {
                asm volatile("cp.async.wait_group 0;\n");
            }
            BAR1();

            uint32_t af[2][4];
#pragma unroll
            for (int f = 0; f < 2; f++) {
                int r = r0 + f * 16;
                af[f][0] = As[buf][r][j0];        af[f][1] = As[buf][r + 8][j0];
                af[f][2] = As[buf][r][j0 + 4];    af[f][3] = As[buf][r + 8][j0 + 4];
            }
            uint32_t bhf[4][2], blf[4][2];
#pragma unroll
            for (int j = 0; j < 4; j++) {
                int r = nb + j * 8;
                bhf[j][0] = Bh[buf][r][j0]; bhf[j][1] = Bh[buf][r][j0 + 4];
                blf[j][0] = Bl[buf][r][j0]; blf[j][1] = Bl[buf][r][j0 + 4];
            }
#pragma unroll
            for (int f = 0; f < 2; f++)
#pragma unroll
                for (int j = 0; j < 4; j++) {
                    mma_f16(acc[f][j], af[f], bhf[j]);
                    mma_f16(acc[f][j], af[f], blf[j]);
                }
            BAR1();
        }

        int q = lane & 3, g = lane >> 2;
#pragma unroll
        for (int f = 0; f < 2; f++) {
            int row0 = bm + wm * 32 + f * 16 + g;
#pragma unroll
            for (int j = 0; j < 4; j++) {
                int col = bn + wn * 32 + j * 8 + 2 * q;
                float2 o0 = {acc[f][j][0], acc[f][j][1]};
                float2 o1 = {acc[f][j][2], acc[f][j][3]};
                *(float2*)(g_pa + (size_t)row0 * L1D + col) = o0;
                *(float2*)(g_pa + (size_t)(row0 + 8) * L1D + col) = o1;
            }
        }
    } else {
        // ================= FFMA fp32 path, k in [K1, NF) =================
        const int t2 = t - 128;
        const int tx = t2 & 15, ty = t2 >> 4;   // 16 x 8, outputs 8x4 per thr

        float acc[8][4];
#pragma unroll
        for (int i = 0; i < 8; i++)
#pragma unroll
            for (int j = 0; j < 4; j++) acc[i][j] = 0.f;

        for (int it = 0; it < NF_IT; it++) {
            const int k0 = K1 + it * 16;
            // A tile 64x16 = 256 f4, 2 per thread, stored transposed
#pragma unroll
            for (int v = 0; v < 2; v++) {
                int lin = t2 + v * 128;
                int r = lin >> 2;
                int q = lin & 3;
                const float4 a4 = *(const float4*)(g_vals + (size_t)(bm + r) * NF + k0 + q * 4);
                Af[q * 4 + 0][r] = a4.x; Af[q * 4 + 1][r] = a4.y;
                Af[q * 4 + 2][r] = a4.z; Af[q * 4 + 3][r] = a4.w;
            }
            // B tile 16x64 = 256 f4, 2 per thread
#pragma unroll
            for (int v = 0; v < 2; v++) {
                int lin = t2 + v * 128;
                int r = lin >> 4;
                int c = (lin & 15) << 2;
                *(float4*)(&Bf[r][c]) = *(const float4*)(ftw + (size_t)(k0 + r) * L1D + bn + c);
            }
            BAR2();

#pragma unroll
            for (int kk = 0; kk < 16; kk++) {
                float4 b4 = *(const float4*)(&Bf[kk][tx << 2]);
                float4 a0 = *(const float4*)(&Af[kk][ty << 3]);
                float4 a1 = *(const float4*)(&Af[kk][(ty << 3) + 4]);
                float a[8] = {a0.x, a0.y, a0.z, a0.w, a1.x, a1.y, a1.z, a1.w};
                float bb[4] = {b4.x, b4.y, b4.z, b4.w};
#pragma unroll
                for (int i = 0; i < 8; i++)
#pragma unroll
                    for (int j = 0; j < 4; j++)
                        acc[i][j] = fmaf(a[i], bb[j], acc[i][j]);
            }
            BAR2();
        }

#pragma unroll
        for (int i = 0; i < 8; i++) {
            int r = bm + (ty << 3) + i;
            float4 o = {acc[i][0], acc[i][1], acc[i][2], acc[i][3]};
            *(float4*)(g_pb + (size_t)r * L1D + bn + (tx << 2)) = o;
        }
    }
}

// ---------------------------------------------------------------------------
// Kernel 3: tail MLP, 4 samples per CTA (256 CTAs) to cut w1 L2 replication.
// 2 warps per sample: warp h=0 does l0c[j<512] (s0*s1), h=1 does l0c[j>=512].
// l0[j] = clip(g_pa[j] + g_pb[j] + ft_b[j], 0, 1), fused.
// ---------------------------------------------------------------------------
__global__ __launch_bounds__(256) void tail_kernel(
    const float* __restrict__ ftb,
    const float* __restrict__ w1, const float* __restrict__ b1,
    const float* __restrict__ w2, const float* __restrict__ b2,
    const float* __restrict__ w3, const float* __restrict__ b3,
    float* __restrict__ out) {
    __shared__ float part[4][2][15];
    __shared__ float h1s[4][15];

    const int t = threadIdx.x, lane = t & 31, wid = t >> 5;
    const int sl = wid >> 1, h = wid & 1;         // sample-local 0..3, half
    const int sample = blockIdx.x * 4 + sl;
    const float* pa = g_pa + (size_t)sample * L1D;
    const float* pb = g_pb + (size_t)sample * L1D;
    const float KCst = 127.f / 128.f;

#define L0(j) fminf(fmaxf(pa[j] + pb[j] + __ldg(ftb + (j)), 0.f), 1.f)

    float c[16];
    if (h == 0) {
#pragma unroll
        for (int i = 0; i < 16; i++) {
            int j1 = i * 32 + lane;
            c[i] = L0(j1) * L0(j1 + 512) * KCst;
        }
    } else {
#pragma unroll
        for (int i = 0; i < 16; i++)
            c[i] = L0(i * 32 + lane) * KCst;
    }

    float a[15];
#pragma unroll
    for (int o = 0; o < 15; o++) a[o] = 0.f;
    const int jbase = h * 512 + lane;
#pragma unroll
    for (int i = 0; i < 16; i++) {
#pragma unroll
        for (int o = 0; o < 15; o++)
            a[o] = fmaf(c[i], __ldg(w1 + (size_t)o * L1D + jbase + i * 32), a[o]);
    }
#pragma unroll
    for (int s = 16; s; s >>= 1)
#pragma unroll
        for (int o = 0; o < 15; o++)
            a[o] += __shfl_xor_sync(0xffffffffu, a[o], s);
    if (lane < 15) part[sl][h][lane] = a[lane];
    __syncthreads();

    if (h == 0) {
        if (lane < 15)
            h1s[sl][lane] = fmaxf(part[sl][0][lane] + part[sl][1][lane] + __ldg(b1 + lane), 0.f);
        __syncwarp();
        float h2 = __ldg(b2 + lane);
#pragma unroll
        for (int k = 0; k < 15; k++)
            h2 = fmaf(h1s[sl][k], __ldg(w2 + lane * 15 + k), h2);
        h2 = fmaxf(h2, 0.f);
        float ov = h2 * __ldg(w3 + lane);
#pragma unroll
        for (int s = 16; s; s >>= 1) ov += __shfl_xor_sync(0xffffffffu, ov, s);
        if (lane == 0) out[sample] = ov + __ldg(b3);
    }
}

// ---------------------------------------------------------------------------
extern "C" void kernel_launch(void* const* d_in, const int* in_sizes, int n_in,
                              void* d_out, int out_size) {
    const float *images = 0, *conv_w = 0, *ft_w = 0, *ft_b = 0;
    const float *w1 = 0, *b1 = 0, *w2 = 0, *b2 = 0, *w3 = 0, *b3 = 0;

    for (int i = 0; i < n_in; i++) {
        const float* p = (const float*)d_in[i];
        switch (in_sizes[i]) {
            case 28311552: images = p; break;
            case 216:      conv_w = p; break;
            case 819200:   ft_w   = p; break;
            case 1024:     ft_b   = p; break;
            case 15360:    w1     = p; break;
            case 15:       b1     = p; break;
            case 480:      w2     = p; break;
            case 32:       if (!b2) b2 = p; else w3 = p; break;
            case 1:        b3     = p; break;
            default: break;
        }
    }
    float* out = (float*)d_out;

    dim3 gt(L1D / 32, K1 / 32);      // 32 x 14
    prep_bt_kernel<<<gt, 256>>>(ft_w);
    conv_act_kernel<<<B_SZ, 128>>>(images, conv_w);

    feat_gemm_kernel<<<256, 256>>>(ft_w);

    tail_kernel<<<B_SZ / 4, 256>>>(ft_b, w1, b1, w2, b2, w3, b3, out);
}

// round 10
// speedup vs baseline: 1.1555x; 1.0686x over previous
#include <cuda_runtime.h>
#include <cuda_fp16.h>
#include <cstdint>
#include <cstddef>

#define B_SZ 1024
#define NF   800
#define L1D  1024
#define NT_IT (NF / 16)   // 50 k-iterations

// Scratch (no allocation allowed — __device__ globals)
__device__ __half g_a[B_SZ * NF];      // vals fp16 (RN), (B,800) row-major
__device__ __half g_bh[L1D * NF];      // ft_w^T hi, (n,k) k-contig
__device__ __half g_bl[L1D * NF];      // ft_w^T lo
__device__ float  g_pa[B_SZ * L1D];    // raw features (no bias/clip)

// ---------------------------------------------------------------------------
// Kernel 0: transpose ft_w (800x1024 -> 1024x800) and split into fp16 hi/lo.
// ---------------------------------------------------------------------------
__global__ __launch_bounds__(256) void prep_bt_kernel(const float* __restrict__ w) {
    __shared__ float ts[32][33];
    int tx = threadIdx.x & 31, ty = threadIdx.x >> 5;   // 32 x 8
    int kbase = blockIdx.y * 32, nbase = blockIdx.x * 32;
#pragma unroll
    for (int i = 0; i < 4; i++)
        ts[ty + i * 8][tx] = w[(size_t)(kbase + ty + i * 8) * L1D + nbase + tx];
    __syncthreads();
#pragma unroll
    for (int i = 0; i < 4; i++) {
        int n = nbase + ty + i * 8;
        int k = kbase + tx;
        float v = ts[tx][ty + i * 8];
        __half h = __float2half_rn(v);
        g_bh[(size_t)n * NF + k] = h;
        g_bl[(size_t)n * NF + k] = __float2half_rn(v - __half2float(h));
    }
}

// ---------------------------------------------------------------------------
// Kernel 1: conv(3x3,s10,p1) + clip + sigmoid gate -> fp16 vals.
// ---------------------------------------------------------------------------
__global__ __launch_bounds__(128) void conv_act_kernel(
    const float* __restrict__ images, const float* __restrict__ conv_w) {
    __shared__ float w[216];
    __shared__ float s[30][3][98];
    int t = threadIdx.x;
    int b = blockIdx.x;
    for (int i = t; i < 216; i += 128) w[i] = conv_w[i];
    for (int i = t; i < 3 * 98; i += 128) s[0][i / 98][i % 98] = 0.f;
    for (int i = t; i < 30 * 3; i += 128) s[i / 3][i % 3][0] = 0.f;
    __syncthreads();

    const float* img = images + (size_t)b * 3 * 96 * 96;
    for (int i = t; i < 29 * 3 * 96; i += 128) {
        int rr = i / 288 + 1; int rem = i - (rr - 1) * 288;
        int c = rem / 96;  int x = rem - c * 96;
        int iy = (rr / 3) * 10 - 1 + rr % 3;
        s[rr][c][x + 1] = __ldg(img + c * 9216 + iy * 96 + x);
    }
    __syncthreads();

    if (t < 100) {
        int oy = t / 10, ox = t - oy * 10;
        float acc[8];
#pragma unroll
        for (int c8 = 0; c8 < 8; c8++) acc[c8] = 0.f;
#pragma unroll
        for (int ky = 0; ky < 3; ky++) {
            const float (*srow)[98] = s[3 * oy + ky];
#pragma unroll
            for (int ic = 0; ic < 3; ic++) {
#pragma unroll
                for (int kx = 0; kx < 3; kx++) {
                    float v = srow[ic][10 * ox + kx];
#pragma unroll
                    for (int c8 = 0; c8 < 8; c8++)
                        acc[c8] = fmaf(v, w[c8 * 27 + ic * 9 + ky * 3 + kx], acc[c8]);
                }
            }
        }
#pragma unroll
        for (int c8 = 0; c8 < 8; c8++) {
            float x  = fminf(fmaxf(acc[c8], -1.f), 1.f);
            float sg = 1.f / (1.f + __expf(-10.f * x));
            float vv = (sg > 0.5f) ? sg : 0.f;
            g_a[(size_t)b * NF + c8 * 100 + t] = __float2half_rn(vv);
        }
    }
}

// ---------------------------------------------------------------------------
// Kernel 2: all-tensor GEMM: D = A*Bh + A*Bl (fp32 accum), m16n8k16.
// BM=64 BN=32 BK=16 -> 512 CTAs (3.46/SM, low wave imbalance), 128 thr,
// 4 warps (2x2), warp tile 32x16. Term-major mma order (RAW distance 4).
// Raw partials -> g_pa.
// ---------------------------------------------------------------------------
__device__ __forceinline__ void mma_f16(float* d, const uint32_t* a, const uint32_t* b) {
    asm volatile(
        "mma.sync.aligned.m16n8k16.row.col.f32.f16.f16.f32 "
        "{%0,%1,%2,%3}, {%4,%5,%6,%7}, {%8,%9}, {%0,%1,%2,%3};\n"
        : "+f"(d[0]), "+f"(d[1]), "+f"(d[2]), "+f"(d[3])
        : "r"(a[0]), "r"(a[1]), "r"(a[2]), "r"(a[3]), "r"(b[0]), "r"(b[1]));
}
#define CP16(dst, src) \
    asm volatile("cp.async.ca.shared.global [%0], [%1], 16;\n" :: "r"(dst), "l"(src))

__global__ __launch_bounds__(128) void feat_mma_kernel() {
    __shared__ uint32_t As[2][64][12];
    __shared__ uint32_t Bh[2][32][12];
    __shared__ uint32_t Bl[2][32][12];

    const int t = threadIdx.x, lane = t & 31, wid = t >> 5;
    const int wm = wid >> 1, wn = wid & 1;           // 2 x 2 warps, 32x16 tiles
    const int bm = blockIdx.y * 64, bn = blockIdx.x * 32;

    float acc[2][2][4];
#pragma unroll
    for (int f = 0; f < 2; f++)
#pragma unroll
        for (int j = 0; j < 2; j++)
#pragma unroll
            for (int e = 0; e < 4; e++) acc[f][j][e] = 0.f;

    // staging: A 128 chunks (64 rows x 2 segs) — one per thread;
    //          B 128 chunks (Bh 32x2 by t<64, Bl 32x2 by t>=64) — one per thread.
    const int arow = t >> 1, aseg = t & 1;
    const int brow = (t & 63) >> 1, bseg = t & 1;
    const __half* a_src = g_a + (size_t)(bm + arow) * NF + aseg * 8;
    const __half* b_src = (t < 64 ? g_bh : g_bl) + (size_t)(bn + brow) * NF + bseg * 8;
    uint32_t a_dst[2], b_dst[2];
#pragma unroll
    for (int s2 = 0; s2 < 2; s2++) {
        a_dst[s2] = (uint32_t)__cvta_generic_to_shared(&As[s2][arow][aseg * 4]);
        b_dst[s2] = (uint32_t)__cvta_generic_to_shared(
            t < 64 ? &Bh[s2][brow][bseg * 4] : &Bl[s2][brow][bseg * 4]);
    }

#define LOAD_STAGE(s2, k0)                                   \
    do {                                                     \
        CP16(a_dst[s2], a_src + (k0));                       \
        CP16(b_dst[s2], b_src + (k0));                       \
        asm volatile("cp.async.commit_group;\n");            \
    } while (0)

    LOAD_STAGE(0, 0);

    const int r0 = wm * 32 + (lane >> 2);
    const int nb = wn * 16 + (lane >> 2);
    const int j0 = lane & 3;

    for (int it = 0; it < NT_IT; it++) {
        int buf = it & 1;
        if (it < NT_IT - 1) {
            LOAD_STAGE(buf ^ 1, (it + 1) * 16);
            asm volatile("cp.async.wait_group 1;\n");
        } else {
            asm volatile("cp.async.wait_group 0;\n");
        }
        __syncthreads();

        uint32_t af[2][4];
#pragma unroll
        for (int f = 0; f < 2; f++) {
            int r = r0 + f * 16;
            af[f][0] = As[buf][r][j0];      af[f][1] = As[buf][r + 8][j0];
            af[f][2] = As[buf][r][j0 + 4];  af[f][3] = As[buf][r + 8][j0 + 4];
        }
        uint32_t bhf[2][2], blf[2][2];
#pragma unroll
        for (int j = 0; j < 2; j++) {
            int r = nb + j * 8;
            bhf[j][0] = Bh[buf][r][j0]; bhf[j][1] = Bh[buf][r][j0 + 4];
            blf[j][0] = Bl[buf][r][j0]; blf[j][1] = Bl[buf][r][j0 + 4];
        }
        // term-major: 4 independent hi-mma, then 4 lo-mma (RAW distance 4)
#pragma unroll
        for (int f = 0; f < 2; f++)
#pragma unroll
            for (int j = 0; j < 2; j++)
                mma_f16(acc[f][j], af[f], bhf[j]);
#pragma unroll
        for (int f = 0; f < 2; f++)
#pragma unroll
            for (int j = 0; j < 2; j++)
                mma_f16(acc[f][j], af[f], blf[j]);
        __syncthreads();
    }

    // epilogue: raw partial -> g_pa
    int q = lane & 3, g = lane >> 2;
#pragma unroll
    for (int f = 0; f < 2; f++) {
        int row0 = bm + wm * 32 + f * 16 + g;
#pragma unroll
        for (int j = 0; j < 2; j++) {
            int col = bn + wn * 16 + j * 8 + 2 * q;
            float2 o0 = {acc[f][j][0], acc[f][j][1]};
            float2 o1 = {acc[f][j][2], acc[f][j][3]};
            *(float2*)(g_pa + (size_t)row0 * L1D + col) = o0;
            *(float2*)(g_pa + (size_t)(row0 + 8) * L1D + col) = o1;
        }
    }
}

// ---------------------------------------------------------------------------
// Kernel 3: tail MLP + fused bias/clip. 8 warps per sample, 1024 CTAs
// (R8's best-measured shape), but only ONE partial buffer read (4 MB).
// l0[j] = clip(g_pa[j] + ft_b[j], 0, 1). Warp q owns e in [4q, 4q+4).
// ---------------------------------------------------------------------------
__global__ __launch_bounds__(256) void tail_kernel(
    const float* __restrict__ ftb,
    const float* __restrict__ w1, const float* __restrict__ b1,
    const float* __restrict__ w2, const float* __restrict__ b2,
    const float* __restrict__ w3, const float* __restrict__ b3,
    float* __restrict__ out) {
    __shared__ float part[8][15];
    __shared__ float h1s[15];

    const int t = threadIdx.x, lane = t & 31, q = t >> 5;
    const int sample = blockIdx.x;
    const float* pa = g_pa + (size_t)sample * L1D;
    const float KCst = 127.f / 128.f;

#define L0(j) fminf(fmaxf(pa[j] + __ldg(ftb + (j)), 0.f), 1.f)

    float c[4];
    if (q < 4) {
#pragma unroll
        for (int i = 0; i < 4; i++) {
            int e = q * 4 + i;
            c[i] = L0(e * 32 + lane) * L0((e + 16) * 32 + lane) * KCst;
        }
    } else {
#pragma unroll
        for (int i = 0; i < 4; i++) {
            int e = (q - 4) * 4 + i;
            c[i] = L0(e * 32 + lane) * KCst;
        }
    }

    float a[15];
#pragma unroll
    for (int o = 0; o < 15; o++) a[o] = 0.f;
    const int jbase = q * 128 + lane;
#pragma unroll
    for (int i = 0; i < 4; i++) {
#pragma unroll
        for (int o = 0; o < 15; o++)
            a[o] = fmaf(c[i], __ldg(w1 + (size_t)o * L1D + jbase + i * 32), a[o]);
    }
#pragma unroll
    for (int s = 16; s; s >>= 1)
#pragma unroll
        for (int o = 0; o < 15; o++)
            a[o] += __shfl_xor_sync(0xffffffffu, a[o], s);
    if (lane < 15) part[q][lane] = a[lane];
    __syncthreads();

    if (q == 0) {
        if (lane < 15) {
            float h = __ldg(b1 + lane);
#pragma unroll
            for (int p = 0; p < 8; p++) h += part[p][lane];
            h1s[lane] = fmaxf(h, 0.f);
        }
        __syncwarp();
        float h2 = __ldg(b2 + lane);
#pragma unroll
        for (int k = 0; k < 15; k++)
            h2 = fmaf(h1s[k], __ldg(w2 + lane * 15 + k), h2);
        h2 = fmaxf(h2, 0.f);
        float ov = h2 * __ldg(w3 + lane);
#pragma unroll
        for (int s = 16; s; s >>= 1) ov += __shfl_xor_sync(0xffffffffu, ov, s);
        if (lane == 0) out[sample] = ov + __ldg(b3);
    }
}

// ---------------------------------------------------------------------------
extern "C" void kernel_launch(void* const* d_in, const int* in_sizes, int n_in,
                              void* d_out, int out_size) {
    const float *images = 0, *conv_w = 0, *ft_w = 0, *ft_b = 0;
    const float *w1 = 0, *b1 = 0, *w2 = 0, *b2 = 0, *w3 = 0, *b3 = 0;

    for (int i = 0; i < n_in; i++) {
        const float* p = (const float*)d_in[i];
        switch (in_sizes[i]) {
            case 28311552: images = p; break;
            case 216:      conv_w = p; break;
            case 819200:   ft_w   = p; break;
            case 1024:     ft_b   = p; break;
            case 15360:    w1     = p; break;
            case 15:       b1     = p; break;
            case 480:      w2     = p; break;
            case 32:       if (!b2) b2 = p; else w3 = p; break;
            case 1:        b3     = p; break;
            default: break;
        }
    }
    float* out = (float*)d_out;

    dim3 gt(L1D / 32, NF / 32);      // 32 x 25
    prep_bt_kernel<<<gt, 256>>>(ft_w);
    conv_act_kernel<<<B_SZ, 128>>>(images, conv_w);

    dim3 g2(L1D / 32, B_SZ / 64);    // 32 x 16 = 512 CTAs
    feat_mma_kernel<<<g2, 128>>>();

    tail_kernel<<<B_SZ, 256>>>(ft_b, w1, b1, w2, b2, w3, b3, out);
}

// round 12
// speedup vs baseline: 1.2393x; 1.0726x over previous
#include <cuda_runtime.h>
#include <cuda_fp16.h>
#include <cstdint>
#include <cstddef>

#define B_SZ 1024
#define NF   800
#define L1D  1024
#define NT_IT (NF / 16)   // 50 k-iterations

// Scratch (no allocation allowed — __device__ globals)
__device__ __half g_a[B_SZ * NF];      // vals fp16 (RN), (B,800) row-major
__device__ __half g_bh[L1D * NF];      // ft_w^T hi, (n,k) k-contig
__device__ __half g_bl[L1D * NF];      // ft_w^T lo
__device__ float  g_pa[B_SZ * L1D];    // raw features (no bias/clip)

// ---------------------------------------------------------------------------
// Kernel 0: transpose ft_w (800x1024 -> 1024x800) and split into fp16 hi/lo.
// ---------------------------------------------------------------------------
__global__ __launch_bounds__(256) void prep_bt_kernel(const float* __restrict__ w) {
    __shared__ float ts[32][33];
    int tx = threadIdx.x & 31, ty = threadIdx.x >> 5;   // 32 x 8
    int kbase = blockIdx.y * 32, nbase = blockIdx.x * 32;
#pragma unroll
    for (int i = 0; i < 4; i++)
        ts[ty + i * 8][tx] = w[(size_t)(kbase + ty + i * 8) * L1D + nbase + tx];
    __syncthreads();
#pragma unroll
    for (int i = 0; i < 4; i++) {
        int n = nbase + ty + i * 8;
        int k = kbase + tx;
        float v = ts[tx][ty + i * 8];
        __half h = __float2half_rn(v);
        g_bh[(size_t)n * NF + k] = h;
        g_bl[(size_t)n * NF + k] = __float2half_rn(v - __half2float(h));
    }
}

// ---------------------------------------------------------------------------
// Kernel 1: conv(3x3,s10,p1) + clip + sigmoid gate -> fp16 vals. 256 threads.
// ---------------------------------------------------------------------------
__global__ __launch_bounds__(256) void conv_act_kernel(
    const float* __restrict__ images, const float* __restrict__ conv_w) {
    __shared__ float w[216];
    __shared__ float s[30][3][98];
    int t = threadIdx.x;
    int b = blockIdx.x;
    for (int i = t; i < 216; i += 256) w[i] = conv_w[i];
    for (int i = t; i < 3 * 98; i += 256) s[0][i / 98][i % 98] = 0.f;
    for (int i = t; i < 30 * 3; i += 256) s[i / 3][i % 3][0] = 0.f;
    __syncthreads();

    const float* img = images + (size_t)b * 3 * 96 * 96;
    for (int i = t; i < 29 * 3 * 96; i += 256) {
        int rr = i / 288 + 1; int rem = i - (rr - 1) * 288;
        int c = rem / 96;  int x = rem - c * 96;
        int iy = (rr / 3) * 10 - 1 + rr % 3;
        s[rr][c][x + 1] = __ldg(img + c * 9216 + iy * 96 + x);
    }
    __syncthreads();

    if (t < 100) {
        int oy = t / 10, ox = t - oy * 10;
        float acc[8];
#pragma unroll
        for (int c8 = 0; c8 < 8; c8++) acc[c8] = 0.f;
#pragma unroll
        for (int ky = 0; ky < 3; ky++) {
            const float (*srow)[98] = s[3 * oy + ky];
#pragma unroll
            for (int ic = 0; ic < 3; ic++) {
#pragma unroll
                for (int kx = 0; kx < 3; kx++) {
                    float v = srow[ic][10 * ox + kx];
#pragma unroll
                    for (int c8 = 0; c8 < 8; c8++)
                        acc[c8] = fmaf(v, w[c8 * 27 + ic * 9 + ky * 3 + kx], acc[c8]);
                }
            }
        }
#pragma unroll
        for (int c8 = 0; c8 < 8; c8++) {
            float x  = fminf(fmaxf(acc[c8], -1.f), 1.f);
            float sg = 1.f / (1.f + __expf(-10.f * x));
            float vv = (sg > 0.5f) ? sg : 0.f;
            g_a[(size_t)b * NF + c8 * 100 + t] = __float2half_rn(vv);
        }
    }
}

// ---------------------------------------------------------------------------
// Kernel 2: all-tensor GEMM, D = A*Bh + A*Bl (fp32 accum), m16n8k16.
// BM=BN=64, 256 CTAs, 8 warps (4 m-tiles x 2 n-groups), warp tile 16x32.
// ldmatrix fragments (NON-trans for B: (n,k) smem IS col-major B),
// 3-stage cp.async pipeline. 48B smem rows: conflict-free, 16B-aligned.
// Raw partials -> g_pa.
// ---------------------------------------------------------------------------
__device__ __forceinline__ void mma_f16(float* d, const uint32_t* a, const uint32_t* b) {
    asm volatile(
        "mma.sync.aligned.m16n8k16.row.col.f32.f16.f16.f32 "
        "{%0,%1,%2,%3}, {%4,%5,%6,%7}, {%8,%9}, {%0,%1,%2,%3};\n"
        : "+f"(d[0]), "+f"(d[1]), "+f"(d[2]), "+f"(d[3])
        : "r"(a[0]), "r"(a[1]), "r"(a[2]), "r"(a[3]), "r"(b[0]), "r"(b[1]));
}
__device__ __forceinline__ void ldm_x4(uint32_t* r, uint32_t addr) {
    asm volatile("ldmatrix.sync.aligned.m8n8.x4.shared.b16 {%0,%1,%2,%3}, [%4];"
        : "=r"(r[0]), "=r"(r[1]), "=r"(r[2]), "=r"(r[3]) : "r"(addr));
}
#define CP16(dst, src) \
    asm volatile("cp.async.ca.shared.global [%0], [%1], 16;\n" :: "r"(dst), "l"(src))

#define STG_BYTES 9216         // per-stage block: A(3072) + Bh(3072) + Bl(3072)

__global__ __launch_bounds__(256) void feat_mma_kernel() {
    __shared__ __align__(16) char smem[3 * STG_BYTES];   // 27648 B
    const uint32_t sb = (uint32_t)__cvta_generic_to_shared(smem);

    const int t = threadIdx.x, lane = t & 31, wid = t >> 5;
    const int wm = wid & 3, wn = wid >> 2;       // 4 m-tiles x 2 n-groups
    const int bm = blockIdx.y * 64, bn = blockIdx.x * 64;

    float acc[4][4];
#pragma unroll
    for (int j = 0; j < 4; j++)
#pragma unroll
        for (int e = 0; e < 4; e++) acc[j][e] = 0.f;

    // ---- staging: 16B chunks. t<128: A chunk + Bl chunk; t>=128: Bh chunk.
    const int c0row = (t & 127) >> 1, c0seg = t & 1;
    const __half* src0 = (t < 128)
        ? g_a  + (size_t)(bm + c0row) * NF + c0seg * 8
        : g_bh + (size_t)(bn + c0row) * NF + c0seg * 8;
    const uint32_t dst0 = sb + ((t < 128) ? 0 : 3072) + c0row * 48 + c0seg * 16;
    const __half* src1 = g_bl + (size_t)(bn + c0row) * NF + c0seg * 8;  // t<128 only
    const uint32_t dst1 = sb + 6144 + c0row * 48 + c0seg * 16;

#define LOAD_STAGE(st, k0)                                        \
    do {                                                          \
        CP16(dst0 + (st) * STG_BYTES, src0 + (k0));               \
        if (t < 128) CP16(dst1 + (st) * STG_BYTES, src1 + (k0));  \
        asm volatile("cp.async.commit_group;\n");                 \
    } while (0)

    LOAD_STAGE(0, 0);
    LOAD_STAGE(1, 16);

    // ---- ldmatrix lane-address offsets (stage-relative) ----
    const int lg = lane >> 3, lr = lane & 7;
    // A x4: tiles [(m0,k0),(m8,k0),(m0,k8),(m8,k8)]
    const uint32_t a_off = (uint32_t)((wm * 16 + (lg & 1) * 8 + lr) * 48 + (lg >> 1) * 16);
    // B x4 NON-trans: address rows = n. tiles [(n0,k0),(n0,k8),(n8,k0),(n8,k8)]
    const uint32_t b_off1 = (uint32_t)((wn * 32 + (lg >> 1) * 8 + lr) * 48 + (lg & 1) * 16);
    const uint32_t b_off2 = b_off1 + 16 * 48;   // n-tiles 2,3

    for (int it = 0; it < NT_IT; it++) {
        const uint32_t stb = sb + (it % 3) * STG_BYTES;
        if (it < NT_IT - 1) {
            asm volatile("cp.async.wait_group 1;\n");
        } else {
            asm volatile("cp.async.wait_group 0;\n");
        }
        __syncthreads();
        if (it < NT_IT - 2) LOAD_STAGE((it + 2) % 3, (it + 2) * 16);

        uint32_t af[4], bh1[4], bh2[4], bl1[4], bl2[4];
        ldm_x4(af,  stb + a_off);
        ldm_x4(bh1, stb + 3072 + b_off1);
        ldm_x4(bh2, stb + 3072 + b_off2);
        ldm_x4(bl1, stb + 6144 + b_off1);
        ldm_x4(bl2, stb + 6144 + b_off2);

        mma_f16(acc[0], af, bh1 + 0);
        mma_f16(acc[1], af, bh1 + 2);
        mma_f16(acc[2], af, bh2 + 0);
        mma_f16(acc[3], af, bh2 + 2);
        mma_f16(acc[0], af, bl1 + 0);
        mma_f16(acc[1], af, bl1 + 2);
        mma_f16(acc[2], af, bl2 + 0);
        mma_f16(acc[3], af, bl2 + 2);
        __syncthreads();
    }

    // epilogue: raw partial -> g_pa. m16n8 frag: rows g, g+8; col = nt*8+2q.
    const int q = lane & 3, g = lane >> 2;
    const int row0 = bm + wm * 16 + g;
#pragma unroll
    for (int nt = 0; nt < 4; nt++) {
        int col = bn + wn * 32 + nt * 8 + 2 * q;
        float2 o0 = {acc[nt][0], acc[nt][1]};
        float2 o1 = {acc[nt][2], acc[nt][3]};
        *(float2*)(g_pa + (size_t)row0 * L1D + col) = o0;
        *(float2*)(g_pa + (size_t)(row0 + 8) * L1D + col) = o1;
    }
}

// ---------------------------------------------------------------------------
// Kernel 3: tail MLP + fused bias/clip. 2 samples per 512-thr CTA (512 CTAs),
// 8 warps per sample. l0[j] = clip(g_pa[j]+ft_b[j], 0, 1).
// ---------------------------------------------------------------------------
__global__ __launch_bounds__(512) void tail_kernel(
    const float* __restrict__ ftb,
    const float* __restrict__ w1, const float* __restrict__ b1,
    const float* __restrict__ w2, const float* __restrict__ b2,
    const float* __restrict__ w3, const float* __restrict__ b3,
    float* __restrict__ out) {
    __shared__ float part[2][8][15];
    __shared__ float h1s[2][15];

    const int t = threadIdx.x, lane = t & 31, wid = t >> 5;
    const int sl = wid >> 3, q = wid & 7;        // sample-local, eighth
    const int sample = blockIdx.x * 2 + sl;
    const float* pa = g_pa + (size_t)sample * L1D;
    const float KCst = 127.f / 128.f;

#define L0(j) fminf(fmaxf(pa[j] + __ldg(ftb + (j)), 0.f), 1.f)

    float c[4];
    if (q < 4) {
#pragma unroll
        for (int i = 0; i < 4; i++) {
            int e = q * 4 + i;
            c[i] = L0(e * 32 + lane) * L0((e + 16) * 32 + lane) * KCst;
        }
    } else {
#pragma unroll
        for (int i = 0; i < 4; i++) {
            int e = (q - 4) * 4 + i;
            c[i] = L0(e * 32 + lane) * KCst;
        }
    }

    float a[15];
#pragma unroll
    for (int o = 0; o < 15; o++) a[o] = 0.f;
    const int jbase = q * 128 + lane;
#pragma unroll
    for (int i = 0; i < 4; i++) {
#pragma unroll
        for (int o = 0; o < 15; o++)
            a[o] = fmaf(c[i], __ldg(w1 + (size_t)o * L1D + jbase + i * 32), a[o]);
    }
#pragma unroll
    for (int s = 16; s; s >>= 1)
#pragma unroll
        for (int o = 0; o < 15; o++)
            a[o] += __shfl_xor_sync(0xffffffffu, a[o], s);
    if (lane < 15) part[sl][q][lane] = a[lane];
    __syncthreads();

    if (q == 0) {
        if (lane < 15) {
            float h = __ldg(b1 + lane);
#pragma unroll
            for (int p = 0; p < 8; p++) h += part[sl][p][lane];
            h1s[sl][lane] = fmaxf(h, 0.f);
        }
        __syncwarp();
        float h2 = __ldg(b2 + lane);
#pragma unroll
        for (int k = 0; k < 15; k++)
            h2 = fmaf(h1s[sl][k], __ldg(w2 + lane * 15 + k), h2);
        h2 = fmaxf(h2, 0.f);
        float ov = h2 * __ldg(w3 + lane);
#pragma unroll
        for (int s = 16; s; s >>= 1) ov += __shfl_xor_sync(0xffffffffu, ov, s);
        if (lane == 0) out[sample] = ov + __ldg(b3);
    }
}

// ---------------------------------------------------------------------------
extern "C" void kernel_launch(void* const* d_in, const int* in_sizes, int n_in,
                              void* d_out, int out_size) {
    const float *images = 0, *conv_w = 0, *ft_w = 0, *ft_b = 0;
    const float *w1 = 0, *b1 = 0, *w2 = 0, *b2 = 0, *w3 = 0, *b3 = 0;

    for (int i = 0; i < n_in; i++) {
        const float* p = (const float*)d_in[i];
        switch (in_sizes[i]) {
            case 28311552: images = p; break;
            case 216:      conv_w = p; break;
            case 819200:   ft_w   = p; break;
            case 1024:     ft_b   = p; break;
            case 15360:    w1     = p; break;
            case 15:       b1     = p; break;
            case 480:      w2     = p; break;
            case 32:       if (!b2) b2 = p; else w3 = p; break;
            case 1:        b3     = p; break;
            default: break;
        }
    }
    float* out = (float*)d_out;

    dim3 gt(L1D / 32, NF / 32);      // 32 x 25
    prep_bt_kernel<<<gt, 256>>>(ft_w);
    conv_act_kernel<<<B_SZ, 256>>>(images, conv_w);

    dim3 g2(L1D / 64, B_SZ / 64);    // 16 x 16 = 256 CTAs
    feat_mma_kernel<<<g2, 256>>>();

    tail_kernel<<<B_SZ / 2, 512>>>(ft_b, w1, b1, w2, b2, w3, b3, out);
}